// round 2
// baseline (speedup 1.0000x reference)
#include <cuda_runtime.h>
#include <math.h>

#define BATCH 65536
#define KCODES 1024
#define DIM 256

// f32 constants matching the reference's rounding
#define DECAY_F 0.99f
#define OMD_F ((float)(1.0 - 0.99))     // 0.009999999776482582f

// ---- output layout: tuple flattened+concatenated, f32 ----
#define OFF_ZQ   0
#define OFF_LOSS (BATCH * DIM)
#define OFF_PERP (BATCH * DIM + 1)
#define OFF_IDX  (BATCH * DIM + 2)
#define OFF_EMB  (OFF_IDX + BATCH)
#define OFF_ECS  (OFF_EMB + KCODES * DIM)
#define OFF_EMAW (OFF_ECS + KCODES)

// ---- device-global scratch ----
__device__ float  g_esq[KCODES];
__device__ float  g_zsq[BATCH];
__device__ int    g_idx[BATCH];
__device__ int    g_cnt[KCODES];
__device__ int    g_cur[KCODES];
__device__ int    g_off[KCODES + 1];
__device__ int    g_rows[BATCH];
__device__ float  g_dw[KCODES * DIM];
__device__ double g_loss;
__device__ float  g_smoothed[KCODES];

// ============================================================
__global__ void init_kernel() {
    int i = blockIdx.x * blockDim.x + threadIdx.x;
    if (i < KCODES) { g_cnt[i] = 0; g_cur[i] = 0; }
    if (i == 0)     g_loss = 0.0;
}

// ============================================================
// Row squared-norms for z_e and embedding. One warp per row.
// ============================================================
__global__ void rowsq_kernel(const float* __restrict__ Z,
                             const float* __restrict__ E) {
    int row  = blockIdx.x * 8 + (threadIdx.x >> 5);
    int lane = threadIdx.x & 31;
    const float* src;
    float* dst;
    if (row < BATCH) {
        src = Z + (size_t)row * DIM;
        dst = g_zsq + row;
    } else {
        int r = row - BATCH;
        src = E + (size_t)r * DIM;
        dst = g_esq + r;
    }
    const float4* p = (const float4*)src;
    float4 v0 = p[lane * 2 + 0];
    float4 v1 = p[lane * 2 + 1];
    float s = v0.x * v0.x + v0.y * v0.y + v0.z * v0.z + v0.w * v0.w
            + v1.x * v1.x + v1.y * v1.y + v1.z * v1.z + v1.w * v1.w;
#pragma unroll
    for (int o = 16; o; o >>= 1) s += __shfl_down_sync(0xffffffffu, s, o);
    if (lane == 0) *dst = s;
}

// ============================================================
// Fused GEMM + argmin using packed fp32 FMA (fma.rn.f32x2).
// 128x128 tile, 16-deep chunks, 8x8 per thread (as 8x4 f32x2 pairs).
// A tile stored DUPLICATED in smem so (a,a) pairs load directly.
// Register-prefetch double buffering: one barrier per chunk.
// ============================================================
#define BM 128
#define BN 128
#define BKT 16
#define LDAD 260                 // duplicated-A row stride (floats)
#define LDB  132                 // B row stride (floats)
#define ABYTES (BKT * LDAD)      // floats per A stage: 4160
#define BBYTES (BKT * LDB)       // floats per B stage: 2112
#define STAGE_FLOATS (ABYTES + BBYTES)
#define ARG_SMEM_BYTES (2 * STAGE_FLOATS * 4)   // 50176 B

__device__ __forceinline__ void fma2(unsigned long long& d,
                                     unsigned long long a,
                                     unsigned long long b) {
    asm("fma.rn.f32x2 %0, %1, %2, %0;" : "+l"(d) : "l"(a), "l"(b));
}

__global__ __launch_bounds__(256, 2)
void argmin_kernel(const float* __restrict__ Z, const float* __restrict__ E) {
    extern __shared__ float sm[];
    float* const Ab[2] = { sm, sm + STAGE_FLOATS };
    float* const Bb[2] = { sm + ABYTES, sm + STAGE_FLOATS + ABYTES };

    const int tid = threadIdx.x;
    const int tr  = tid >> 4;        // 0..15 row group
    const int tc  = tid & 15;        // 0..15 col group
    const int r   = tid >> 2;        // 0..63 (load row, + 64 for second)
    const int c4  = tid & 3;         // which float4 of the 16-col chunk
    const int rowBase = blockIdx.x * BM;

    float zs[8];
#pragma unroll
    for (int i = 0; i < 8; i++) zs[i] = g_zsq[rowBase + tr * 8 + i];

    float bestd[8];
    int   bestk[8];
#pragma unroll
    for (int i = 0; i < 8; i++) { bestd[i] = 3.4e38f; bestk[i] = 0; }

    float4 nA0, nA1, nB0, nB1;

    // ---- prefetch + store chunk 0 ----
    {
        const float* zp = Z + (size_t)(rowBase + r) * DIM + c4 * 4;
        const float* ep = E + (size_t)r * DIM + c4 * 4;
        nA0 = *(const float4*)zp;
        nA1 = *(const float4*)(zp + (size_t)64 * DIM);
        nB0 = *(const float4*)ep;
        nB1 = *(const float4*)(ep + (size_t)64 * DIM);
    }
    {
        float* A = Ab[0]; float* B = Bb[0];
#pragma unroll
        for (int l = 0; l < 2; l++) {
            int rr = r + 64 * l;
            float4 va = l ? nA1 : nA0;
            float4 vb = l ? nB1 : nB0;
            *(float2*)&A[(c4 * 4 + 0) * LDAD + 2 * rr] = make_float2(va.x, va.x);
            *(float2*)&A[(c4 * 4 + 1) * LDAD + 2 * rr] = make_float2(va.y, va.y);
            *(float2*)&A[(c4 * 4 + 2) * LDAD + 2 * rr] = make_float2(va.z, va.z);
            *(float2*)&A[(c4 * 4 + 3) * LDAD + 2 * rr] = make_float2(va.w, va.w);
            B[(c4 * 4 + 0) * LDB + rr] = vb.x;
            B[(c4 * 4 + 1) * LDB + rr] = vb.y;
            B[(c4 * 4 + 2) * LDB + rr] = vb.z;
            B[(c4 * 4 + 3) * LDB + rr] = vb.w;
        }
    }
    __syncthreads();

    unsigned long long acc[8][4];
#pragma unroll
    for (int i = 0; i < 8; i++)
#pragma unroll
        for (int j = 0; j < 4; j++) acc[i][j] = 0ull;

    for (int c = 0; c < 128; c++) {
        const int lastc = (c == 127);

        // prefetch next chunk (global -> regs)
        if (!lastc) {
            const int nc = c + 1;
            const int nt = nc >> 4, dt = nc & 15;
            const float* zp = Z + (size_t)(rowBase + r) * DIM + dt * 16 + c4 * 4;
            const float* ep = E + (size_t)(nt * 128 + r) * DIM + dt * 16 + c4 * 4;
            nA0 = *(const float4*)zp;
            nA1 = *(const float4*)(zp + (size_t)64 * DIM);
            nB0 = *(const float4*)ep;
            nB1 = *(const float4*)(ep + (size_t)64 * DIM);
        }

        // compute on current buffer
        {
            const float* A = Ab[c & 1];
            const float* B = Bb[c & 1];
#pragma unroll
            for (int kk = 0; kk < BKT; kk++) {
                const ulonglong2* ap = (const ulonglong2*)(A + kk * LDAD + tr * 16);
                const ulonglong2* bp = (const ulonglong2*)(B + kk * LDB + tc * 8);
                ulonglong2 aa0 = ap[0], aa1 = ap[1], aa2 = ap[2], aa3 = ap[3];
                ulonglong2 bb0 = bp[0], bb1 = bp[1];
                unsigned long long av[8] = {aa0.x, aa0.y, aa1.x, aa1.y,
                                            aa2.x, aa2.y, aa3.x, aa3.y};
                unsigned long long bv[4] = {bb0.x, bb0.y, bb1.x, bb1.y};
#pragma unroll
                for (int i = 0; i < 8; i++)
#pragma unroll
                    for (int j = 0; j < 4; j++)
                        fma2(acc[i][j], av[i], bv[j]);
            }
        }

        // per-code-tile argmin epilogue, then reset acc
        if ((c & 15) == 15) {
            const int codeBase = (c >> 4) * BN;
#pragma unroll
            for (int jp = 0; jp < 4; jp++) {
#pragma unroll
                for (int h = 0; h < 2; h++) {
                    int   code = codeBase + tc * 8 + jp * 2 + h;
                    float esq  = g_esq[code];
#pragma unroll
                    for (int i = 0; i < 8; i++) {
                        unsigned long long v = acc[i][jp];
                        float dot = h ? __uint_as_float((unsigned)(v >> 32))
                                      : __uint_as_float((unsigned)v);
                        float dist = (zs[i] + esq) - 2.0f * dot;
                        if (dist < bestd[i]) { bestd[i] = dist; bestk[i] = code; }
                    }
                }
            }
#pragma unroll
            for (int i = 0; i < 8; i++)
#pragma unroll
                for (int j = 0; j < 4; j++) acc[i][j] = 0ull;
        }

        // store prefetched chunk into the other buffer
        if (!lastc) {
            float* A = Ab[(c + 1) & 1];
            float* B = Bb[(c + 1) & 1];
#pragma unroll
            for (int l = 0; l < 2; l++) {
                int rr = r + 64 * l;
                float4 va = l ? nA1 : nA0;
                float4 vb = l ? nB1 : nB0;
                *(float2*)&A[(c4 * 4 + 0) * LDAD + 2 * rr] = make_float2(va.x, va.x);
                *(float2*)&A[(c4 * 4 + 1) * LDAD + 2 * rr] = make_float2(va.y, va.y);
                *(float2*)&A[(c4 * 4 + 2) * LDAD + 2 * rr] = make_float2(va.z, va.z);
                *(float2*)&A[(c4 * 4 + 3) * LDAD + 2 * rr] = make_float2(va.w, va.w);
                B[(c4 * 4 + 0) * LDB + rr] = vb.x;
                B[(c4 * 4 + 1) * LDB + rr] = vb.y;
                B[(c4 * 4 + 2) * LDB + rr] = vb.z;
                B[(c4 * 4 + 3) * LDB + rr] = vb.w;
            }
        }
        __syncthreads();
    }

    // reduce across the 16 threads (tc) sharing each row; tie -> lower index
#pragma unroll
    for (int off = 8; off; off >>= 1) {
#pragma unroll
        for (int i = 0; i < 8; i++) {
            float od = __shfl_down_sync(0xffffffffu, bestd[i], off, 16);
            int   ok = __shfl_down_sync(0xffffffffu, bestk[i], off, 16);
            if (od < bestd[i] || (od == bestd[i] && ok < bestk[i])) {
                bestd[i] = od; bestk[i] = ok;
            }
        }
    }
    if (tc == 0) {
#pragma unroll
        for (int i = 0; i < 8; i++) g_idx[rowBase + tr * 8 + i] = bestk[i];
    }
}

// ============================================================
// z_q_st elementwise + idx output + loss (one double atomic/block).
// No dw/cs atomics here anymore.
// ============================================================
__global__ void zq_kernel(const float* __restrict__ Z,
                          const float* __restrict__ E,
                          float* __restrict__ out) {
    __shared__ double lred[8];
    int warp = threadIdx.x >> 5;
    int lane = threadIdx.x & 31;
    int row  = blockIdx.x * 8 + warp;
    int ci   = g_idx[row];

    const float4* zp = (const float4*)(Z + (size_t)row * DIM);
    const float4* qp = (const float4*)(E + (size_t)ci * DIM);
    float4*       op = (float4*)(out + OFF_ZQ + (size_t)row * DIM);

    float sq = 0.0f;
#pragma unroll
    for (int l = 0; l < 2; l++) {
        float4 z = zp[lane * 2 + l];
        float4 q = qp[lane * 2 + l];
        float dx = q.x - z.x, dy = q.y - z.y, dz = q.z - z.z, dw4 = q.w - z.w;
        float4 o;
        o.x = z.x + dx; o.y = z.y + dy; o.z = z.z + dz; o.w = z.w + dw4;
        op[lane * 2 + l] = o;
        sq += dx * dx + dy * dy + dz * dz + dw4 * dw4;
    }
#pragma unroll
    for (int o = 16; o; o >>= 1) sq += __shfl_down_sync(0xffffffffu, sq, o);
    if (lane == 0) {
        lred[warp] = (double)sq;
        out[OFF_IDX + row] = (float)ci;
    }
    __syncthreads();
    if (threadIdx.x == 0) {
        double s = 0.0;
#pragma unroll
        for (int w = 0; w < 8; w++) s += lred[w];
        atomicAdd(&g_loss, s);
    }
}

// ============================================================
// Counting sort: histogram -> scan -> scatter row lists.
// ============================================================
__global__ void hist_kernel() {
    int i = blockIdx.x * blockDim.x + threadIdx.x;
    if (i < BATCH) atomicAdd(&g_cnt[g_idx[i]], 1);
}

__global__ void scan_kernel() {
    __shared__ int s[KCODES];
    int t = threadIdx.x;
    s[t] = g_cnt[t];
    __syncthreads();
#pragma unroll
    for (int o = 1; o < KCODES; o <<= 1) {
        int v = s[t];
        int u = (t >= o) ? s[t - o] : 0;
        __syncthreads();
        s[t] = v + u;
        __syncthreads();
    }
    g_off[t + 1] = s[t];
    if (t == 0) g_off[0] = 0;
}

__global__ void scatter_kernel() {
    int i = blockIdx.x * blockDim.x + threadIdx.x;
    if (i < BATCH) {
        int c = g_idx[i];
        int pos = atomicAdd(&g_cur[c], 1);
        g_rows[g_off[c] + pos] = i;
    }
}

// ============================================================
// dw[k,:] = sum of z rows assigned to code k (no atomics).
// One block per code; thread d owns dimension d.
// ============================================================
__global__ void dw_kernel(const float* __restrict__ Z) {
    int k = blockIdx.x;
    int d = threadIdx.x;
    int s = g_off[k], e = g_off[k + 1];
    float acc = 0.0f;
    for (int i = s; i < e; i++)
        acc += Z[(size_t)g_rows[i] * DIM + d];
    g_dw[k * DIM + d] = acc;
}

// ============================================================
// Finalize K-sized stats.
// ============================================================
__global__ void finalize_kernel(const float* __restrict__ ecs_in,
                                float* __restrict__ out) {
    __shared__ float red[KCODES];
    int k = threadIdx.x;

    float cs   = (float)g_cnt[k];
    float necs = DECAY_F * ecs_in[k] + OMD_F * cs;
    out[OFF_ECS + k] = necs;

    red[k] = necs;
    __syncthreads();
#pragma unroll
    for (int s = 512; s; s >>= 1) {
        if (k < s) red[k] += red[k + s];
        __syncthreads();
    }
    float n = red[0];
    __syncthreads();

    float p = cs * (1.0f / (float)BATCH);
    red[k] = p * logf(p + 1e-10f);
    __syncthreads();
#pragma unroll
    for (int s = 512; s; s >>= 1) {
        if (k < s) red[k] += red[k + s];
        __syncthreads();
    }
    if (k == 0) {
        out[OFF_PERP] = expf(-red[0]);
        out[OFF_LOSS] = (float)(0.25 * (g_loss / ((double)BATCH * (double)DIM)));
    }

    float smoothed = (necs + 1e-5f) / (n + (float)(KCODES * 1e-5)) * n;
    g_smoothed[k] = smoothed;
}

// ============================================================
__global__ void emaw_kernel(const float* __restrict__ ema_w,
                            float* __restrict__ out) {
    int idx = blockIdx.x * DIM + threadIdx.x;
    int k   = idx >> 8;
    float w = DECAY_F * ema_w[idx] + OMD_F * g_dw[idx];
    out[OFF_EMAW + idx] = w;
    out[OFF_EMB + idx]  = w / g_smoothed[k];
}

// ============================================================
extern "C" void kernel_launch(void* const* d_in, const int* in_sizes, int n_in,
                              void* d_out, int out_size) {
    const float* z_e  = (const float*)d_in[0];
    const float* emb  = (const float*)d_in[1];
    const float* ecs  = (const float*)d_in[2];
    const float* emaw = (const float*)d_in[3];
    float* out = (float*)d_out;

    cudaFuncSetAttribute(argmin_kernel,
                         cudaFuncAttributeMaxDynamicSharedMemorySize,
                         ARG_SMEM_BYTES);

    init_kernel<<<(KCODES + 255) / 256, 256>>>();
    rowsq_kernel<<<(BATCH + KCODES) / 8, 256>>>(z_e, emb);
    argmin_kernel<<<BATCH / BM, 256, ARG_SMEM_BYTES>>>(z_e, emb);
    zq_kernel<<<BATCH / 8, 256>>>(z_e, emb, out);
    hist_kernel<<<BATCH / 256, 256>>>();
    scan_kernel<<<1, KCODES>>>();
    scatter_kernel<<<BATCH / 256, 256>>>();
    dw_kernel<<<KCODES, DIM>>>(z_e);
    finalize_kernel<<<1, KCODES>>>(ecs, out);
    emaw_kernel<<<KCODES, DIM>>>(emaw, out);
}

// round 4
// speedup vs baseline: 2.5935x; 2.5935x over previous
#include <cuda_runtime.h>
#include <cuda_fp16.h>
#include <math.h>

#define BATCH 65536
#define KCODES 1024
#define DIM 256

#define DECAY_F 0.99f
#define OMD_F ((float)(1.0 - 0.99))

// ---- output layout: tuple flattened+concatenated, f32 ----
#define OFF_ZQ   0
#define OFF_LOSS (BATCH * DIM)
#define OFF_PERP (BATCH * DIM + 1)
#define OFF_IDX  (BATCH * DIM + 2)
#define OFF_EMB  (OFF_IDX + BATCH)
#define OFF_ECS  (OFF_EMB + KCODES * DIM)
#define OFF_EMAW (OFF_ECS + KCODES)

#define MARGIN 0.3f

// ---- device-global scratch ----
__device__ __half g_zh[BATCH * DIM];     // fp16(-2 * z)
__device__ __half g_eh[KCODES * DIM];    // fp16(e)
__device__ float  g_esq[KCODES];
__device__ float  g_zsq[BATCH];
__device__ int    g_idx[BATCH];
__device__ int    g_namb;
__device__ int    g_amb[BATCH];
__device__ unsigned long long g_fb[BATCH];
__device__ int    g_cnt[KCODES];
__device__ int    g_cur[KCODES];
__device__ int    g_off[KCODES + 1];
__device__ int    g_rows[BATCH];
__device__ float  g_dw[KCODES * DIM];
__device__ double g_loss;
__device__ float  g_smoothed[KCODES];

// ================= helpers =================
__device__ __forceinline__ unsigned smem_u32(const void* p) {
    unsigned a;
    asm("{ .reg .u64 t; cvta.to.shared.u64 t, %1; cvt.u32.u64 %0, t; }"
        : "=r"(a) : "l"(p));
    return a;
}

__device__ __forceinline__ void cp16(unsigned dst, const void* src) {
    asm volatile("cp.async.cg.shared.global [%0], [%1], 16;"
                 :: "r"(dst), "l"(__cvta_generic_to_global(src)));
}
#define CP_COMMIT() asm volatile("cp.async.commit_group;" ::: "memory")
#define CP_WAIT(n)  asm volatile("cp.async.wait_group %0;" :: "n"(n) : "memory")

#define LDSM4(r0, r1, r2, r3, addr) \
    asm volatile("ldmatrix.sync.aligned.m8n8.x4.shared.b16 {%0,%1,%2,%3}, [%4];" \
        : "=r"(r0), "=r"(r1), "=r"(r2), "=r"(r3) : "r"(addr))

#define MMA16816(d, a, b) \
    asm volatile("mma.sync.aligned.m16n8k16.row.col.f32.f16.f16.f32 " \
        "{%0,%1,%2,%3}, {%4,%5,%6,%7}, {%8,%9}, {%0,%1,%2,%3};" \
        : "+f"((d)[0]), "+f"((d)[1]), "+f"((d)[2]), "+f"((d)[3]) \
        : "r"((a)[0]), "r"((a)[1]), "r"((a)[2]), "r"((a)[3]), \
          "r"((b)[0]), "r"((b)[1]))

// smem layout (bytes)
#define SM_ESQ  0
#define SM_A    4096
#define SM_B    (SM_A + 65536)
#define SM_TOTAL (SM_B + 2 * 65536)    // 200704

// ============================================================
__global__ void init_kernel() {
    int i = blockIdx.x * blockDim.x + threadIdx.x;
    if (i < KCODES) { g_cnt[i] = 0; g_cur[i] = 0; }
    if (i == 0)     { g_loss = 0.0; g_namb = 0; }
}

// ============================================================
// Convert to fp16 (+fold -2 into z) and compute row norms.
// ============================================================
__global__ void convert_kernel(const float* __restrict__ Z,
                               const float* __restrict__ E) {
    int row  = blockIdx.x * 8 + (threadIdx.x >> 5);
    int lane = threadIdx.x & 31;
    const float* src;
    __half* dst;
    float* sqdst;
    float scale;
    if (row < BATCH) {
        src = Z + (size_t)row * DIM;
        dst = g_zh + (size_t)row * DIM;
        sqdst = g_zsq + row; scale = -2.0f;
    } else {
        int r = row - BATCH;
        src = E + (size_t)r * DIM;
        dst = g_eh + (size_t)r * DIM;
        sqdst = g_esq + r; scale = 1.0f;
    }
    float4 a0 = ((const float4*)src)[lane * 2 + 0];
    float4 a1 = ((const float4*)src)[lane * 2 + 1];
    float x[8] = {a0.x, a0.y, a0.z, a0.w, a1.x, a1.y, a1.z, a1.w};
    float sq = 0.0f;
    unsigned w[4];
#pragma unroll
    for (int p = 0; p < 4; p++) {
        sq += x[2*p] * x[2*p] + x[2*p+1] * x[2*p+1];
        __half h0 = __float2half_rn(scale * x[2*p]);
        __half h1 = __float2half_rn(scale * x[2*p+1]);
        w[p] = (unsigned)__half_as_ushort(h0)
             | ((unsigned)__half_as_ushort(h1) << 16);
    }
    ((uint4*)dst)[lane] = make_uint4(w[0], w[1], w[2], w[3]);
#pragma unroll
    for (int o = 16; o; o >>= 1) sq += __shfl_down_sync(0xffffffffu, sq, o);
    if (lane == 0) *sqdst = sq;
}

// ============================================================
// HMMA distance + fused top-2 argmin.
// CTA: 128 rows x all 1024 codes. A resident, B double-buffered.
// score = -2*z.e (fp16 MMA, fp32 accum); dist = esq + score.
// Rows with best2-best1 < MARGIN go to exact fallback.
// ============================================================
__device__ __forceinline__ void load_B_tile(unsigned sb, int nt, int buf, int tid) {
#pragma unroll 4
    for (int it = 0; it < 16; it++) {
        int idx = tid + it * 256;
        int row = idx >> 5, u = idx & 31;
        const void* src = g_eh + ((size_t)(nt * 128 + row) << 8) + u * 8;
        unsigned dst = sb + SM_B + buf * 65536 + row * 512 + ((u ^ (row & 7)) << 4);
        cp16(dst, src);
    }
}

#define UPD(s, d, c) do { \
    if ((d) < best1[s] || ((d) == best1[s] && (c) < bk[s])) { \
        best2[s] = best1[s]; best1[s] = (d); bk[s] = (c); \
    } else if ((d) < best2[s]) best2[s] = (d); } while (0)

__global__ void __launch_bounds__(256, 1)
mma_argmin_kernel() {
    extern __shared__ char smem[];
    const unsigned sb = smem_u32(smem);
    const int tid  = threadIdx.x;
    const int lane = tid & 31;
    const int warp = tid >> 5;
    const int warp_m = warp & 3;       // 0..3 (32 rows each)
    const int warp_n = warp >> 2;      // 0..1 (64 codes each)
    const int rowBase = blockIdx.x * 128;

    float* s_esq = (float*)(smem + SM_ESQ);
    for (int i = tid; i < KCODES; i += 256) s_esq[i] = g_esq[i];

    // ---- A resident: 128 x 256 fp16, swizzled 16B units ----
#pragma unroll 4
    for (int it = 0; it < 16; it++) {
        int idx = tid + it * 256;
        int row = idx >> 5, u = idx & 31;
        const void* src = g_zh + ((size_t)(rowBase + row) << 8) + u * 8;
        unsigned dst = sb + SM_A + row * 512 + ((u ^ (row & 7)) << 4);
        cp16(dst, src);
    }
    load_B_tile(sb, 0, 0, tid);
    CP_COMMIT();                 // G0: A + B0
    load_B_tile(sb, 1, 1, tid);
    CP_COMMIT();                 // G1: B1

    // ldmatrix per-lane base addresses
    unsigned a_base[2], b_base[4];
    int a_x[2], b_x[4];
    const int a_uo = lane >> 4;          // 0/1
    const int b_uo = (lane >> 3) & 1;    // 0/1
#pragma unroll
    for (int mi = 0; mi < 2; mi++) {
        int r = warp_m * 32 + mi * 16 + (lane & 15);
        a_base[mi] = sb + SM_A + r * 512;
        a_x[mi] = r & 7;
    }
#pragma unroll
    for (int nq = 0; nq < 4; nq++) {
        int r = warp_n * 64 + nq * 16 + (lane & 7) + ((lane & 16) ? 8 : 0);
        b_base[nq] = sb + SM_B + r * 512;
        b_x[nq] = r & 7;
    }

    float best1[4], best2[4];
    int   bk[4];
#pragma unroll
    for (int s = 0; s < 4; s++) { best1[s] = 3.4e38f; best2[s] = 3.4e38f; bk[s] = 0; }

    for (int nt = 0; nt < 8; nt++) {
        if (nt < 7) { CP_WAIT(1); } else { CP_WAIT(0); }
        __syncthreads();

        const unsigned boff = (unsigned)((nt & 1) * 65536);
        float acc[2][8][4];
#pragma unroll
        for (int mi = 0; mi < 2; mi++)
#pragma unroll
            for (int ni = 0; ni < 8; ni++)
#pragma unroll
                for (int q = 0; q < 4; q++) acc[mi][ni][q] = 0.0f;

#pragma unroll
        for (int ks = 0; ks < 16; ks++) {
            unsigned af[2][4];
#pragma unroll
            for (int mi = 0; mi < 2; mi++) {
                unsigned u = (unsigned)((ks * 2 + a_uo) ^ a_x[mi]) << 4;
                LDSM4(af[mi][0], af[mi][1], af[mi][2], af[mi][3], a_base[mi] + u);
            }
            unsigned bf[8][2];
#pragma unroll
            for (int nq = 0; nq < 4; nq++) {
                unsigned u = (unsigned)((ks * 2 + b_uo) ^ b_x[nq]) << 4;
                unsigned q0, q1, q2, q3;
                LDSM4(q0, q1, q2, q3, b_base[nq] + boff + u);
                bf[2*nq][0] = q0;   bf[2*nq][1] = q1;
                bf[2*nq+1][0] = q2; bf[2*nq+1][1] = q3;
            }
#pragma unroll
            for (int mi = 0; mi < 2; mi++)
#pragma unroll
                for (int ni = 0; ni < 8; ni++)
                    MMA16816(acc[mi][ni], af[mi], bf[ni]);
        }

        // epilogue: fold esq, update per-thread top-2
        const int cbase = nt * 128 + warp_n * 64 + (lane & 3) * 2;
#pragma unroll
        for (int ni = 0; ni < 8; ni++) {
            int c0 = cbase + ni * 8;
            float e0 = s_esq[c0], e1 = s_esq[c0 + 1];
#pragma unroll
            for (int mi = 0; mi < 2; mi++) {
                float d0 = acc[mi][ni][0] + e0;
                float d1 = acc[mi][ni][1] + e1;
                float d2 = acc[mi][ni][2] + e0;
                float d3 = acc[mi][ni][3] + e1;
                int s = mi * 2;
                UPD(s, d0, c0); UPD(s, d1, c0 + 1);
                UPD(s + 1, d2, c0); UPD(s + 1, d3, c0 + 1);
            }
        }
        __syncthreads();
        if (nt + 2 < 8) { load_B_tile(sb, nt + 2, nt & 1, tid); CP_COMMIT(); }
    }

    // quad (lane%4) butterfly merge of top-2
#pragma unroll
    for (int off = 1; off <= 2; off <<= 1) {
#pragma unroll
        for (int s = 0; s < 4; s++) {
            float o1 = __shfl_xor_sync(0xffffffffu, best1[s], off);
            float o2 = __shfl_xor_sync(0xffffffffu, best2[s], off);
            int   ok = __shfl_xor_sync(0xffffffffu, bk[s], off);
            if (o1 < best1[s] || (o1 == best1[s] && ok < bk[s])) {
                best2[s] = fminf(best1[s], o2);
                best1[s] = o1; bk[s] = ok;
            } else {
                best2[s] = fminf(best2[s], o1);
            }
        }
    }

    // cross-warp (warp_n) merge via smem (reuse A region)
    float* f1 = (float*)(smem + SM_A);
    float* f2 = f1 + 256;
    int*   kk = (int*)(f2 + 256);
    if ((lane & 3) == 0) {
        int rq = lane >> 2;
#pragma unroll
        for (int s = 0; s < 4; s++) {
            int rl = warp_m * 32 + (s >> 1) * 16 + (s & 1) * 8 + rq;
            f1[warp_n * 128 + rl] = best1[s];
            f2[warp_n * 128 + rl] = best2[s];
            kk[warp_n * 128 + rl] = bk[s];
        }
    }
    __syncthreads();
    if (tid < 128) {
        float a1 = f1[tid],      a2 = f2[tid];      int ak = kk[tid];
        float b1 = f1[128+tid],  b2 = f2[128+tid];  int bkk = kk[128+tid];
        float m1, m2; int mk;
        if (b1 < a1 || (b1 == a1 && bkk < ak)) { m1 = b1; mk = bkk; m2 = fminf(a1, b2); }
        else                                   { m1 = a1; mk = ak;  m2 = fminf(a2, b1); }
        int row = rowBase + tid;
        g_idx[row] = mk;
        if (m2 - m1 < MARGIN) {
            int p = atomicAdd(&g_namb, 1);
            g_amb[p] = row;
        }
    }
}

// ============================================================
// Exact fp32 recompute for ambiguous rows (8 rows per pass).
// ============================================================
__global__ void __launch_bounds__(256)
fallback_kernel(const float* __restrict__ Z, const float* __restrict__ E) {
    __shared__ float zrow[8][DIM];
    __shared__ unsigned long long red[256];
    __shared__ int s_rid[8];
    const int namb = g_namb;
    for (int base = blockIdx.x * 8; base < namb; base += gridDim.x * 8) {
        const int m = min(8, namb - base);
        if (threadIdx.x < m) s_rid[threadIdx.x] = g_amb[base + threadIdx.x];
        __syncthreads();
        for (int t = threadIdx.x; t < m * 64; t += 256) {
            int r = t >> 6, q = t & 63;
            ((float4*)zrow[r])[q] = ((const float4*)(Z + (size_t)s_rid[r] * DIM))[q];
        }
        __syncthreads();

        float zs[8];
#pragma unroll
        for (int r = 0; r < 8; r++) zs[r] = (r < m) ? g_zsq[s_rid[r]] : 0.0f;

        unsigned long long best[8];
#pragma unroll
        for (int r = 0; r < 8; r++) best[r] = ~0ull;

        for (int rep = 0; rep < 4; rep++) {
            int k = threadIdx.x + rep * 256;
            float esq = g_esq[k];
            const float4* ep = (const float4*)(E + (size_t)k * DIM);
            float dot[8];
#pragma unroll
            for (int r = 0; r < 8; r++) dot[r] = 0.0f;
            for (int d = 0; d < 64; d++) {
                float4 e = ep[d];
#pragma unroll
                for (int r = 0; r < 8; r++) {
                    const float* z = &zrow[r][d * 4];
                    dot[r] += e.x * z[0] + e.y * z[1] + e.z * z[2] + e.w * z[3];
                }
            }
#pragma unroll
            for (int r = 0; r < 8; r++) {
                float dist = (zs[r] + esq) - 2.0f * dot[r];
                unsigned long long key =
                    ((unsigned long long)__float_as_uint(dist) << 32) | (unsigned)k;
                if (key < best[r]) best[r] = key;
            }
        }
        for (int r = 0; r < m; r++) {
            red[threadIdx.x] = best[r];
            __syncthreads();
#pragma unroll
            for (int s = 128; s; s >>= 1) {
                if (threadIdx.x < s && red[threadIdx.x + s] < red[threadIdx.x])
                    red[threadIdx.x] = red[threadIdx.x + s];
                __syncthreads();
            }
            if (threadIdx.x == 0) g_fb[s_rid[r]] = red[0];
            __syncthreads();
        }
        __syncthreads();
    }
}

__global__ void fixup_kernel() {
    for (int i = blockIdx.x * blockDim.x + threadIdx.x; i < g_namb;
         i += gridDim.x * blockDim.x) {
        int row = g_amb[i];
        g_idx[row] = (int)(g_fb[row] & 0xFFFFFFFFull);
    }
}

// ============================================================
// z_q_st elementwise + idx output + loss.
// ============================================================
__global__ void zq_kernel(const float* __restrict__ Z,
                          const float* __restrict__ E,
                          float* __restrict__ out) {
    __shared__ double lred[8];
    int warp = threadIdx.x >> 5;
    int lane = threadIdx.x & 31;
    int row  = blockIdx.x * 8 + warp;
    int ci   = g_idx[row];

    const float4* zp = (const float4*)(Z + (size_t)row * DIM);
    const float4* qp = (const float4*)(E + (size_t)ci * DIM);
    float4*       op = (float4*)(out + OFF_ZQ + (size_t)row * DIM);

    float sq = 0.0f;
#pragma unroll
    for (int l = 0; l < 2; l++) {
        float4 z = zp[lane * 2 + l];
        float4 q = qp[lane * 2 + l];
        float dx = q.x - z.x, dy = q.y - z.y, dz = q.z - z.z, dw4 = q.w - z.w;
        float4 o;
        o.x = z.x + dx; o.y = z.y + dy; o.z = z.z + dz; o.w = z.w + dw4;
        op[lane * 2 + l] = o;
        sq += dx * dx + dy * dy + dz * dz + dw4 * dw4;
    }
#pragma unroll
    for (int o = 16; o; o >>= 1) sq += __shfl_down_sync(0xffffffffu, sq, o);
    if (lane == 0) {
        lred[warp] = (double)sq;
        out[OFF_IDX + row] = (float)ci;
    }
    __syncthreads();
    if (threadIdx.x == 0) {
        double s = 0.0;
#pragma unroll
        for (int w = 0; w < 8; w++) s += lred[w];
        atomicAdd(&g_loss, s);
    }
}

// ============================================================
// Counting sort: histogram -> scan -> scatter -> dw (no float atomics).
// ============================================================
__global__ void hist_kernel() {
    int i = blockIdx.x * blockDim.x + threadIdx.x;
    if (i < BATCH) atomicAdd(&g_cnt[g_idx[i]], 1);
}

__global__ void scan_kernel() {
    __shared__ int s[KCODES];
    int t = threadIdx.x;
    s[t] = g_cnt[t];
    __syncthreads();
#pragma unroll
    for (int o = 1; o < KCODES; o <<= 1) {
        int v = s[t];
        int u = (t >= o) ? s[t - o] : 0;
        __syncthreads();
        s[t] = v + u;
        __syncthreads();
    }
    g_off[t + 1] = s[t];
    if (t == 0) g_off[0] = 0;
}

__global__ void scatter_kernel() {
    int i = blockIdx.x * blockDim.x + threadIdx.x;
    if (i < BATCH) {
        int c = g_idx[i];
        int pos = atomicAdd(&g_cur[c], 1);
        g_rows[g_off[c] + pos] = i;
    }
}

__global__ void dw_kernel(const float* __restrict__ Z) {
    int k = blockIdx.x;
    int d = threadIdx.x;
    int s = g_off[k], e = g_off[k + 1];
    float acc = 0.0f;
    for (int i = s; i < e; i++)
        acc += Z[(size_t)g_rows[i] * DIM + d];
    g_dw[k * DIM + d] = acc;
}

// ============================================================
__global__ void finalize_kernel(const float* __restrict__ ecs_in,
                                float* __restrict__ out) {
    __shared__ float red[KCODES];
    int k = threadIdx.x;

    float cs   = (float)g_cnt[k];
    float necs = DECAY_F * ecs_in[k] + OMD_F * cs;
    out[OFF_ECS + k] = necs;

    red[k] = necs;
    __syncthreads();
#pragma unroll
    for (int s = 512; s; s >>= 1) {
        if (k < s) red[k] += red[k + s];
        __syncthreads();
    }
    float n = red[0];
    __syncthreads();

    float p = cs * (1.0f / (float)BATCH);
    red[k] = p * logf(p + 1e-10f);
    __syncthreads();
#pragma unroll
    for (int s = 512; s; s >>= 1) {
        if (k < s) red[k] += red[k + s];
        __syncthreads();
    }
    if (k == 0) {
        out[OFF_PERP] = expf(-red[0]);
        out[OFF_LOSS] = (float)(0.25 * (g_loss / ((double)BATCH * (double)DIM)));
    }

    float smoothed = (necs + 1e-5f) / (n + (float)(KCODES * 1e-5)) * n;
    g_smoothed[k] = smoothed;
}

__global__ void emaw_kernel(const float* __restrict__ ema_w,
                            float* __restrict__ out) {
    int idx = blockIdx.x * DIM + threadIdx.x;
    int k   = idx >> 8;
    float w = DECAY_F * ema_w[idx] + OMD_F * g_dw[idx];
    out[OFF_EMAW + idx] = w;
    out[OFF_EMB + idx]  = w / g_smoothed[k];
}

// ============================================================
extern "C" void kernel_launch(void* const* d_in, const int* in_sizes, int n_in,
                              void* d_out, int out_size) {
    const float* z_e  = (const float*)d_in[0];
    const float* emb  = (const float*)d_in[1];
    const float* ecs  = (const float*)d_in[2];
    const float* emaw = (const float*)d_in[3];
    float* out = (float*)d_out;

    cudaFuncSetAttribute(mma_argmin_kernel,
                         cudaFuncAttributeMaxDynamicSharedMemorySize, SM_TOTAL);

    init_kernel<<<(KCODES + 255) / 256, 256>>>();
    convert_kernel<<<(BATCH + KCODES) / 8, 256>>>(z_e, emb);
    mma_argmin_kernel<<<BATCH / 128, 256, SM_TOTAL>>>();
    fallback_kernel<<<512, 256>>>(z_e, emb);
    fixup_kernel<<<16, 256>>>();
    zq_kernel<<<BATCH / 8, 256>>>(z_e, emb, out);
    hist_kernel<<<BATCH / 256, 256>>>();
    scan_kernel<<<1, KCODES>>>();
    scatter_kernel<<<BATCH / 256, 256>>>();
    dw_kernel<<<KCODES, DIM>>>(z_e);
    finalize_kernel<<<1, KCODES>>>(ecs, out);
    emaw_kernel<<<KCODES, DIM>>>(emaw, out);
}

// round 5
// speedup vs baseline: 2.8037x; 1.0810x over previous
#include <cuda_runtime.h>
#include <cuda_fp16.h>
#include <math.h>

#define BATCH 65536
#define KCODES 1024
#define DIM 256

#define DECAY_F 0.99f
#define OMD_F ((float)(1.0 - 0.99))

// ---- output layout: tuple flattened+concatenated, f32 ----
#define OFF_ZQ   0
#define OFF_LOSS (BATCH * DIM)
#define OFF_PERP (BATCH * DIM + 1)
#define OFF_IDX  (BATCH * DIM + 2)
#define OFF_EMB  (OFF_IDX + BATCH)
#define OFF_ECS  (OFF_EMB + KCODES * DIM)
#define OFF_EMAW (OFF_ECS + KCODES)

#define MARGIN 0.18f

// ---- device-global scratch ----
__device__ __half g_zh[BATCH * DIM];     // fp16(-2 * z)
__device__ __half g_eh[KCODES * DIM];    // fp16(e)
__device__ float  g_esq[KCODES];
__device__ float  g_zsq[BATCH];
__device__ int    g_idx[BATCH];
__device__ int    g_namb;
__device__ int    g_amb[BATCH];
__device__ unsigned long long g_fb[BATCH];
__device__ int    g_cnt[KCODES];
__device__ int    g_cur[KCODES];
__device__ int    g_off[KCODES + 1];
__device__ int    g_rows[BATCH];
__device__ float  g_dw[KCODES * DIM];
__device__ double g_loss;
__device__ float  g_smoothed[KCODES];

// ================= helpers =================
__device__ __forceinline__ unsigned smem_u32(const void* p) {
    unsigned a;
    asm("{ .reg .u64 t; cvta.to.shared.u64 t, %1; cvt.u32.u64 %0, t; }"
        : "=r"(a) : "l"(p));
    return a;
}

__device__ __forceinline__ void cp16(unsigned dst, const void* src) {
    asm volatile("cp.async.cg.shared.global [%0], [%1], 16;"
                 :: "r"(dst), "l"(__cvta_generic_to_global(src)));
}
#define CP_COMMIT() asm volatile("cp.async.commit_group;" ::: "memory")
#define CP_WAIT(n)  asm volatile("cp.async.wait_group %0;" :: "n"(n) : "memory")

#define LDSM4(r0, r1, r2, r3, addr) \
    asm volatile("ldmatrix.sync.aligned.m8n8.x4.shared.b16 {%0,%1,%2,%3}, [%4];" \
        : "=r"(r0), "=r"(r1), "=r"(r2), "=r"(r3) : "r"(addr))

#define MMA16816(d, a, b) \
    asm volatile("mma.sync.aligned.m16n8k16.row.col.f32.f16.f16.f32 " \
        "{%0,%1,%2,%3}, {%4,%5,%6,%7}, {%8,%9}, {%0,%1,%2,%3};" \
        : "+f"((d)[0]), "+f"((d)[1]), "+f"((d)[2]), "+f"((d)[3]) \
        : "r"((a)[0]), "r"((a)[1]), "r"((a)[2]), "r"((a)[3]), \
          "r"((b)[0]), "r"((b)[1]))

// smem layout (bytes)
#define SM_ESQ  0
#define SM_A    4096
#define SM_B    (SM_A + 65536)
#define SM_TOTAL (SM_B + 2 * 65536)    // 200704

// ============================================================
__global__ void init_kernel() {
    int i = blockIdx.x * blockDim.x + threadIdx.x;
    if (i < KCODES) { g_cnt[i] = 0; g_cur[i] = 0; }
    if (i == 0)     { g_loss = 0.0; g_namb = 0; }
}

// ============================================================
// fp16 conversion (+fold -2 into z) and row norms; split into
// two launches so mma_argmin is the 4th launch (ncu profiles #4).
// ============================================================
__device__ __forceinline__ void conv_row(const float* src, __half* dst,
                                         float* sqdst, float scale, int lane) {
    float4 a0 = ((const float4*)src)[lane * 2 + 0];
    float4 a1 = ((const float4*)src)[lane * 2 + 1];
    float x[8] = {a0.x, a0.y, a0.z, a0.w, a1.x, a1.y, a1.z, a1.w};
    float sq = 0.0f;
    unsigned w[4];
#pragma unroll
    for (int p = 0; p < 4; p++) {
        sq += x[2*p] * x[2*p] + x[2*p+1] * x[2*p+1];
        __half h0 = __float2half_rn(scale * x[2*p]);
        __half h1 = __float2half_rn(scale * x[2*p+1]);
        w[p] = (unsigned)__half_as_ushort(h0)
             | ((unsigned)__half_as_ushort(h1) << 16);
    }
    ((uint4*)dst)[lane] = make_uint4(w[0], w[1], w[2], w[3]);
#pragma unroll
    for (int o = 16; o; o >>= 1) sq += __shfl_down_sync(0xffffffffu, sq, o);
    if (lane == 0) *sqdst = sq;
}

__global__ void convert_z_kernel(const float* __restrict__ Z) {
    int row  = blockIdx.x * 8 + (threadIdx.x >> 5);
    int lane = threadIdx.x & 31;
    conv_row(Z + (size_t)row * DIM, g_zh + (size_t)row * DIM,
             g_zsq + row, -2.0f, lane);
}

__global__ void convert_e_kernel(const float* __restrict__ E) {
    int row  = blockIdx.x * 8 + (threadIdx.x >> 5);
    int lane = threadIdx.x & 31;
    conv_row(E + (size_t)row * DIM, g_eh + (size_t)row * DIM,
             g_esq + row, 1.0f, lane);
}

// ============================================================
// HMMA distance + fused top-2 argmin. 512 threads, 16 warps (4x4),
// warp tile 32 rows x 32 codes. A resident, B double-buffered.
// ============================================================
__device__ __forceinline__ void load_B_tile(unsigned sb, int nt, int buf, int tid) {
#pragma unroll
    for (int it = 0; it < 8; it++) {
        int idx = tid + it * 512;
        int row = idx >> 5, u = idx & 31;
        const void* src = g_eh + ((size_t)(nt * 128 + row) << 8) + u * 8;
        unsigned dst = sb + SM_B + buf * 65536 + row * 512 + ((u ^ (row & 7)) << 4);
        cp16(dst, src);
    }
}

#define UPD(s, d, c) do { \
    if ((d) < best1[s] || ((d) == best1[s] && (c) < bk[s])) { \
        best2[s] = best1[s]; best1[s] = (d); bk[s] = (c); \
    } else if ((d) < best2[s]) best2[s] = (d); } while (0)

__global__ void __launch_bounds__(512, 1)
mma_argmin_kernel() {
    extern __shared__ char smem[];
    const unsigned sb = smem_u32(smem);
    const int tid  = threadIdx.x;
    const int lane = tid & 31;
    const int warp = tid >> 5;
    const int warp_m = warp & 3;       // 0..3 (32 rows each)
    const int warp_n = warp >> 2;      // 0..3 (32 codes each)
    const int rowBase = blockIdx.x * 128;

    float* s_esq = (float*)(smem + SM_ESQ);
    for (int i = tid; i < KCODES; i += 512) s_esq[i] = g_esq[i];

    // ---- A resident: 128 x 256 fp16, swizzled 16B units ----
#pragma unroll
    for (int it = 0; it < 8; it++) {
        int idx = tid + it * 512;
        int row = idx >> 5, u = idx & 31;
        const void* src = g_zh + ((size_t)(rowBase + row) << 8) + u * 8;
        unsigned dst = sb + SM_A + row * 512 + ((u ^ (row & 7)) << 4);
        cp16(dst, src);
    }
    load_B_tile(sb, 0, 0, tid);
    CP_COMMIT();                 // G0: A + B0
    load_B_tile(sb, 1, 1, tid);
    CP_COMMIT();                 // G1: B1

    // ldmatrix per-lane base addresses
    unsigned a_base[2], b_base[2];
    int a_x[2], b_x[2];
    const int a_uo = lane >> 4;          // 0/1
    const int b_uo = (lane >> 3) & 1;    // 0/1
#pragma unroll
    for (int mi = 0; mi < 2; mi++) {
        int r = warp_m * 32 + mi * 16 + (lane & 15);
        a_base[mi] = sb + SM_A + r * 512;
        a_x[mi] = r & 7;
    }
#pragma unroll
    for (int nq = 0; nq < 2; nq++) {
        int r = warp_n * 32 + nq * 16 + (lane & 7) + ((lane & 16) ? 8 : 0);
        b_base[nq] = sb + SM_B + r * 512;
        b_x[nq] = r & 7;
    }

    float best1[4], best2[4];
    int   bk[4];
#pragma unroll
    for (int s = 0; s < 4; s++) { best1[s] = 3.4e38f; best2[s] = 3.4e38f; bk[s] = 0; }

    for (int nt = 0; nt < 8; nt++) {
        if (nt < 7) { CP_WAIT(1); } else { CP_WAIT(0); }
        __syncthreads();

        const unsigned boff = (unsigned)((nt & 1) * 65536);
        float acc[2][4][4];
#pragma unroll
        for (int mi = 0; mi < 2; mi++)
#pragma unroll
            for (int ni = 0; ni < 4; ni++)
#pragma unroll
                for (int q = 0; q < 4; q++) acc[mi][ni][q] = 0.0f;

#pragma unroll
        for (int ks = 0; ks < 16; ks++) {
            unsigned af[2][4];
#pragma unroll
            for (int mi = 0; mi < 2; mi++) {
                unsigned u = (unsigned)((ks * 2 + a_uo) ^ a_x[mi]) << 4;
                LDSM4(af[mi][0], af[mi][1], af[mi][2], af[mi][3], a_base[mi] + u);
            }
            unsigned bf[4][2];
#pragma unroll
            for (int nq = 0; nq < 2; nq++) {
                unsigned u = (unsigned)((ks * 2 + b_uo) ^ b_x[nq]) << 4;
                unsigned q0, q1, q2, q3;
                LDSM4(q0, q1, q2, q3, b_base[nq] + boff + u);
                bf[2*nq][0] = q0;   bf[2*nq][1] = q1;
                bf[2*nq+1][0] = q2; bf[2*nq+1][1] = q3;
            }
#pragma unroll
            for (int mi = 0; mi < 2; mi++)
#pragma unroll
                for (int ni = 0; ni < 4; ni++)
                    MMA16816(acc[mi][ni], af[mi], bf[ni]);
        }

        // epilogue: fold esq, update per-thread top-2
        const int cbase = nt * 128 + warp_n * 32 + (lane & 3) * 2;
#pragma unroll
        for (int ni = 0; ni < 4; ni++) {
            int c0 = cbase + ni * 8;
            float e0 = s_esq[c0], e1 = s_esq[c0 + 1];
#pragma unroll
            for (int mi = 0; mi < 2; mi++) {
                float d0 = acc[mi][ni][0] + e0;
                float d1 = acc[mi][ni][1] + e1;
                float d2 = acc[mi][ni][2] + e0;
                float d3 = acc[mi][ni][3] + e1;
                int s = mi * 2;
                UPD(s, d0, c0); UPD(s, d1, c0 + 1);
                UPD(s + 1, d2, c0); UPD(s + 1, d3, c0 + 1);
            }
        }
        __syncthreads();
        if (nt + 2 < 8) { load_B_tile(sb, nt + 2, nt & 1, tid); CP_COMMIT(); }
    }

    // quad (lane%4) butterfly merge of top-2
#pragma unroll
    for (int off = 1; off <= 2; off <<= 1) {
#pragma unroll
        for (int s = 0; s < 4; s++) {
            float o1 = __shfl_xor_sync(0xffffffffu, best1[s], off);
            float o2 = __shfl_xor_sync(0xffffffffu, best2[s], off);
            int   ok = __shfl_xor_sync(0xffffffffu, bk[s], off);
            if (o1 < best1[s] || (o1 == best1[s] && ok < bk[s])) {
                best2[s] = fminf(best1[s], o2);
                best1[s] = o1; bk[s] = ok;
            } else {
                best2[s] = fminf(best2[s], o1);
            }
        }
    }

    // cross-warp (4 warp_n columns) merge via smem (reuse A region)
    float* f1 = (float*)(smem + SM_A);
    float* f2 = f1 + 512;
    int*   kk = (int*)(f2 + 512);
    if ((lane & 3) == 0) {
        int rq = lane >> 2;
#pragma unroll
        for (int s = 0; s < 4; s++) {
            int rl = warp_m * 32 + (s >> 1) * 16 + (s & 1) * 8 + rq;
            f1[warp_n * 128 + rl] = best1[s];
            f2[warp_n * 128 + rl] = best2[s];
            kk[warp_n * 128 + rl] = bk[s];
        }
    }
    __syncthreads();
    if (tid < 128) {
        float m1 = f1[tid], m2 = f2[tid];
        int   mk = kk[tid];
#pragma unroll
        for (int w = 1; w < 4; w++) {
            float b1 = f1[w * 128 + tid], b2 = f2[w * 128 + tid];
            int   bkk = kk[w * 128 + tid];
            if (b1 < m1 || (b1 == m1 && bkk < mk)) {
                m2 = fminf(m1, b2); m1 = b1; mk = bkk;
            } else {
                m2 = fminf(m2, b1);
            }
        }
        int row = rowBase + tid;
        g_idx[row] = mk;
        if (m2 - m1 < MARGIN) {
            int p = atomicAdd(&g_namb, 1);
            g_amb[p] = row;
            g_fb[row] = ~0ull;
        }
    }
}

// ============================================================
// Exact fp32 recompute for ambiguous rows.
// Grid 2048 = 512 row-groups x 4 code-quarters; merge via
// atomicMin on u64 (distbits<<32 | code) -> first-index ties.
// ============================================================
__global__ void __launch_bounds__(256)
fallback_kernel(const float* __restrict__ Z, const float* __restrict__ E) {
    __shared__ float zrow[8][DIM];
    __shared__ unsigned long long red[256];
    __shared__ int s_rid[8];
    const int grp = blockIdx.x >> 2;
    const int qtr = blockIdx.x & 3;
    const int namb = g_namb;
    const int k = qtr * 256 + threadIdx.x;
    const float esq = g_esq[k];
    const float4* ep = (const float4*)(E + (size_t)k * DIM);

    for (int base = grp * 8; base < namb; base += 512 * 8) {
        const int m = min(8, namb - base);
        if (threadIdx.x < m) s_rid[threadIdx.x] = g_amb[base + threadIdx.x];
        __syncthreads();
        for (int t = threadIdx.x; t < m * 64; t += 256) {
            int r = t >> 6, q = t & 63;
            ((float4*)zrow[r])[q] = ((const float4*)(Z + (size_t)s_rid[r] * DIM))[q];
        }
        __syncthreads();

        float zs[8];
#pragma unroll
        for (int r = 0; r < 8; r++) zs[r] = (r < m) ? g_zsq[s_rid[r]] : 0.0f;

        float dot[8];
#pragma unroll
        for (int r = 0; r < 8; r++) dot[r] = 0.0f;
        for (int d = 0; d < 64; d++) {
            float4 e = ep[d];
#pragma unroll
            for (int r = 0; r < 8; r++) {
                const float* z = &zrow[r][d * 4];
                dot[r] += e.x * z[0] + e.y * z[1] + e.z * z[2] + e.w * z[3];
            }
        }
        for (int r = 0; r < m; r++) {
            float dist = (zs[r] + esq) - 2.0f * dot[r];
            red[threadIdx.x] =
                ((unsigned long long)__float_as_uint(dist) << 32) | (unsigned)k;
            __syncthreads();
#pragma unroll
            for (int s = 128; s; s >>= 1) {
                if (threadIdx.x < s && red[threadIdx.x + s] < red[threadIdx.x])
                    red[threadIdx.x] = red[threadIdx.x + s];
                __syncthreads();
            }
            if (threadIdx.x == 0)
                atomicMin(&g_fb[s_rid[r]], red[0]);
            __syncthreads();
        }
        __syncthreads();
    }
}

__global__ void fixup_kernel() {
    for (int i = blockIdx.x * blockDim.x + threadIdx.x; i < g_namb;
         i += gridDim.x * blockDim.x) {
        int row = g_amb[i];
        g_idx[row] = (int)(g_fb[row] & 0xFFFFFFFFull);
    }
}

// ============================================================
// z_q_st elementwise + idx output + loss.
// ============================================================
__global__ void zq_kernel(const float* __restrict__ Z,
                          const float* __restrict__ E,
                          float* __restrict__ out) {
    __shared__ double lred[8];
    int warp = threadIdx.x >> 5;
    int lane = threadIdx.x & 31;
    int row  = blockIdx.x * 8 + warp;
    int ci   = g_idx[row];

    const float4* zp = (const float4*)(Z + (size_t)row * DIM);
    const float4* qp = (const float4*)(E + (size_t)ci * DIM);
    float4*       op = (float4*)(out + OFF_ZQ + (size_t)row * DIM);

    float sq = 0.0f;
#pragma unroll
    for (int l = 0; l < 2; l++) {
        float4 z = zp[lane * 2 + l];
        float4 q = qp[lane * 2 + l];
        float dx = q.x - z.x, dy = q.y - z.y, dz = q.z - z.z, dw4 = q.w - z.w;
        float4 o;
        o.x = z.x + dx; o.y = z.y + dy; o.z = z.z + dz; o.w = z.w + dw4;
        op[lane * 2 + l] = o;
        sq += dx * dx + dy * dy + dz * dz + dw4 * dw4;
    }
#pragma unroll
    for (int o = 16; o; o >>= 1) sq += __shfl_down_sync(0xffffffffu, sq, o);
    if (lane == 0) {
        lred[warp] = (double)sq;
        out[OFF_IDX + row] = (float)ci;
    }
    __syncthreads();
    if (threadIdx.x == 0) {
        double s = 0.0;
#pragma unroll
        for (int w = 0; w < 8; w++) s += lred[w];
        atomicAdd(&g_loss, s);
    }
}

// ============================================================
// Counting sort: histogram -> scan -> scatter -> dw.
// ============================================================
__global__ void hist_kernel() {
    int i = blockIdx.x * blockDim.x + threadIdx.x;
    if (i < BATCH) atomicAdd(&g_cnt[g_idx[i]], 1);
}

__global__ void scan_kernel() {
    __shared__ int s[KCODES];
    int t = threadIdx.x;
    s[t] = g_cnt[t];
    __syncthreads();
#pragma unroll
    for (int o = 1; o < KCODES; o <<= 1) {
        int v = s[t];
        int u = (t >= o) ? s[t - o] : 0;
        __syncthreads();
        s[t] = v + u;
        __syncthreads();
    }
    g_off[t + 1] = s[t];
    if (t == 0) g_off[0] = 0;
}

__global__ void scatter_kernel() {
    int i = blockIdx.x * blockDim.x + threadIdx.x;
    if (i < BATCH) {
        int c = g_idx[i];
        int pos = atomicAdd(&g_cur[c], 1);
        g_rows[g_off[c] + pos] = i;
    }
}

__global__ void dw_kernel(const float* __restrict__ Z) {
    int k = blockIdx.x;
    int d = threadIdx.x;
    int s = g_off[k], e = g_off[k + 1];
    float acc0 = 0.0f, acc1 = 0.0f;
    int i = s;
    for (; i + 1 < e; i += 2) {
        acc0 += Z[(size_t)g_rows[i] * DIM + d];
        acc1 += Z[(size_t)g_rows[i + 1] * DIM + d];
    }
    if (i < e) acc0 += Z[(size_t)g_rows[i] * DIM + d];
    g_dw[k * DIM + d] = acc0 + acc1;
}

// ============================================================
__global__ void finalize_kernel(const float* __restrict__ ecs_in,
                                float* __restrict__ out) {
    __shared__ float red[KCODES];
    int k = threadIdx.x;

    float cs   = (float)g_cnt[k];
    float necs = DECAY_F * ecs_in[k] + OMD_F * cs;
    out[OFF_ECS + k] = necs;

    red[k] = necs;
    __syncthreads();
#pragma unroll
    for (int s = 512; s; s >>= 1) {
        if (k < s) red[k] += red[k + s];
        __syncthreads();
    }
    float n = red[0];
    __syncthreads();

    float p = cs * (1.0f / (float)BATCH);
    red[k] = p * logf(p + 1e-10f);
    __syncthreads();
#pragma unroll
    for (int s = 512; s; s >>= 1) {
        if (k < s) red[k] += red[k + s];
        __syncthreads();
    }
    if (k == 0) {
        out[OFF_PERP] = expf(-red[0]);
        out[OFF_LOSS] = (float)(0.25 * (g_loss / ((double)BATCH * (double)DIM)));
    }

    float smoothed = (necs + 1e-5f) / (n + (float)(KCODES * 1e-5)) * n;
    g_smoothed[k] = smoothed;
}

__global__ void emaw_kernel(const float* __restrict__ ema_w,
                            float* __restrict__ out) {
    int idx = blockIdx.x * DIM + threadIdx.x;
    int k   = idx >> 8;
    float w = DECAY_F * ema_w[idx] + OMD_F * g_dw[idx];
    out[OFF_EMAW + idx] = w;
    out[OFF_EMB + idx]  = w / g_smoothed[k];
}

// ============================================================
extern "C" void kernel_launch(void* const* d_in, const int* in_sizes, int n_in,
                              void* d_out, int out_size) {
    const float* z_e  = (const float*)d_in[0];
    const float* emb  = (const float*)d_in[1];
    const float* ecs  = (const float*)d_in[2];
    const float* emaw = (const float*)d_in[3];
    float* out = (float*)d_out;

    cudaFuncSetAttribute(mma_argmin_kernel,
                         cudaFuncAttributeMaxDynamicSharedMemorySize, SM_TOTAL);

    init_kernel<<<(KCODES + 255) / 256, 256>>>();
    convert_z_kernel<<<BATCH / 8, 256>>>(z_e);
    convert_e_kernel<<<KCODES / 8, 256>>>(emb);
    mma_argmin_kernel<<<BATCH / 128, 512, SM_TOTAL>>>();   // 4th launch -> profiled
    fallback_kernel<<<2048, 256>>>(z_e, emb);
    fixup_kernel<<<16, 256>>>();
    zq_kernel<<<BATCH / 8, 256>>>(z_e, emb, out);
    hist_kernel<<<BATCH / 256, 256>>>();
    scan_kernel<<<1, KCODES>>>();
    scatter_kernel<<<BATCH / 256, 256>>>();
    dw_kernel<<<KCODES, DIM>>>(z_e);
    finalize_kernel<<<1, KCODES>>>(ecs, out);
    emaw_kernel<<<KCODES, DIM>>>(emaw, out);
}

// round 6
// speedup vs baseline: 2.9343x; 1.0466x over previous
#include <cuda_runtime.h>
#include <cuda_fp16.h>
#include <math.h>

#define BATCH 65536
#define KCODES 1024
#define DIM 256

#define DECAY_F 0.99f
#define OMD_F ((float)(1.0 - 0.99))

// ---- output layout: tuple flattened+concatenated, f32 ----
#define OFF_ZQ   0
#define OFF_LOSS (BATCH * DIM)
#define OFF_PERP (BATCH * DIM + 1)
#define OFF_IDX  (BATCH * DIM + 2)
#define OFF_EMB  (OFF_IDX + BATCH)
#define OFF_ECS  (OFF_EMB + KCODES * DIM)
#define OFF_EMAW (OFF_ECS + KCODES)

#define MARGIN 0.18f

// ---- device-global scratch ----
__device__ __half g_zh[BATCH * DIM];     // fp16(-2 * z)
__device__ __half g_eh[KCODES * DIM];    // fp16(e)
__device__ float  g_et[DIM * KCODES];    // fp32 E transposed: [d][k]
__device__ float  g_esq[KCODES];
__device__ float  g_zsq[BATCH];
__device__ int    g_idx[BATCH];
__device__ int    g_namb;
__device__ int    g_amb[BATCH];
__device__ unsigned long long g_fb[BATCH];
__device__ int    g_cnt[KCODES];
__device__ int    g_cur[KCODES];
__device__ int    g_off[KCODES + 1];
__device__ int    g_rows[BATCH];
__device__ float  g_dw[KCODES * DIM];
__device__ double g_loss;
__device__ float  g_smoothed[KCODES];

// ================= helpers =================
__device__ __forceinline__ unsigned smem_u32(const void* p) {
    unsigned a;
    asm("{ .reg .u64 t; cvta.to.shared.u64 t, %1; cvt.u32.u64 %0, t; }"
        : "=r"(a) : "l"(p));
    return a;
}

__device__ __forceinline__ void cp16(unsigned dst, const void* src) {
    asm volatile("cp.async.cg.shared.global [%0], [%1], 16;"
                 :: "r"(dst), "l"(__cvta_generic_to_global(src)));
}
#define CP_COMMIT() asm volatile("cp.async.commit_group;" ::: "memory")
#define CP_WAIT(n)  asm volatile("cp.async.wait_group %0;" :: "n"(n) : "memory")

#define LDSM4(r0, r1, r2, r3, addr) \
    asm volatile("ldmatrix.sync.aligned.m8n8.x4.shared.b16 {%0,%1,%2,%3}, [%4];" \
        : "=r"(r0), "=r"(r1), "=r"(r2), "=r"(r3) : "r"(addr))

#define MMA16816(d, a, b) \
    asm volatile("mma.sync.aligned.m16n8k16.row.col.f32.f16.f16.f32 " \
        "{%0,%1,%2,%3}, {%4,%5,%6,%7}, {%8,%9}, {%0,%1,%2,%3};" \
        : "+f"((d)[0]), "+f"((d)[1]), "+f"((d)[2]), "+f"((d)[3]) \
        : "r"((a)[0]), "r"((a)[1]), "r"((a)[2]), "r"((a)[3]), \
          "r"((b)[0]), "r"((b)[1]))

// smem layout (bytes) — 100KB total -> 2 CTAs/SM
#define SM_ESQ  0
#define SM_A    4096
#define SM_B    (SM_A + 32768)
#define SM_TOTAL (SM_B + 2 * 32768)    // 102400

// ============================================================
__global__ void init_kernel() {
    int i = blockIdx.x * blockDim.x + threadIdx.x;
    if (i < KCODES) { g_cnt[i] = 0; g_cur[i] = 0; }
    if (i == 0)     { g_loss = 0.0; g_namb = 0; }
}

// ============================================================
// fp16 conversion (+fold -2 into z) and row norms.
// convert_e also writes fp32 E^T for the coalesced fallback.
// ============================================================
__global__ void convert_z_kernel(const float* __restrict__ Z) {
    int row  = blockIdx.x * 8 + (threadIdx.x >> 5);
    int lane = threadIdx.x & 31;
    const float* src = Z + (size_t)row * DIM;
    float4 a0 = ((const float4*)src)[lane * 2 + 0];
    float4 a1 = ((const float4*)src)[lane * 2 + 1];
    float x[8] = {a0.x, a0.y, a0.z, a0.w, a1.x, a1.y, a1.z, a1.w};
    float sq = 0.0f;
    unsigned w[4];
#pragma unroll
    for (int p = 0; p < 4; p++) {
        sq += x[2*p] * x[2*p] + x[2*p+1] * x[2*p+1];
        __half h0 = __float2half_rn(-2.0f * x[2*p]);
        __half h1 = __float2half_rn(-2.0f * x[2*p+1]);
        w[p] = (unsigned)__half_as_ushort(h0)
             | ((unsigned)__half_as_ushort(h1) << 16);
    }
    ((uint4*)(g_zh + (size_t)row * DIM))[lane] = make_uint4(w[0], w[1], w[2], w[3]);
#pragma unroll
    for (int o = 16; o; o >>= 1) sq += __shfl_down_sync(0xffffffffu, sq, o);
    if (lane == 0) g_zsq[row] = sq;
}

__global__ void convert_e_kernel(const float* __restrict__ E) {
    int row  = blockIdx.x * 8 + (threadIdx.x >> 5);
    int lane = threadIdx.x & 31;
    const float* src = E + (size_t)row * DIM;
    float4 a0 = ((const float4*)src)[lane * 2 + 0];
    float4 a1 = ((const float4*)src)[lane * 2 + 1];
    float x[8] = {a0.x, a0.y, a0.z, a0.w, a1.x, a1.y, a1.z, a1.w};
    float sq = 0.0f;
    unsigned w[4];
#pragma unroll
    for (int p = 0; p < 4; p++) {
        sq += x[2*p] * x[2*p] + x[2*p+1] * x[2*p+1];
        __half h0 = __float2half_rn(x[2*p]);
        __half h1 = __float2half_rn(x[2*p+1]);
        w[p] = (unsigned)__half_as_ushort(h0)
             | ((unsigned)__half_as_ushort(h1) << 16);
    }
    ((uint4*)(g_eh + (size_t)row * DIM))[lane] = make_uint4(w[0], w[1], w[2], w[3]);
    // transposed fp32 copy for the fallback (one-time 1MB)
#pragma unroll
    for (int j = 0; j < 8; j++)
        g_et[(size_t)(lane * 8 + j) * KCODES + row] = x[j];
#pragma unroll
    for (int o = 16; o; o >>= 1) sq += __shfl_down_sync(0xffffffffu, sq, o);
    if (lane == 0) g_esq[row] = sq;
}

// ============================================================
// HMMA distance + fused top-2 argmin.
// CTA: 64 rows x 1024 codes, 16 B-tiles of 64 codes, 256 threads
// (8 warps = 2 m-groups x 4 n-groups, warp tile 32r x 16c).
// smem 100KB -> 2 CTAs/SM. A resident; B double-buffered cp.async.
// ============================================================
__device__ __forceinline__ void load_B_tile(unsigned sb, int nt, int buf, int tid) {
#pragma unroll
    for (int it = 0; it < 8; it++) {
        int idx = tid + it * 256;          // 0..2047
        int row = idx >> 5, u = idx & 31;
        const void* src = g_eh + ((size_t)(nt * 64 + row) << 8) + u * 8;
        unsigned dst = sb + SM_B + buf * 32768 + row * 512 + ((u ^ (row & 7)) << 4);
        cp16(dst, src);
    }
}

#define UPD(s, d, c) do { \
    if ((d) < best1[s] || ((d) == best1[s] && (c) < bk[s])) { \
        best2[s] = best1[s]; best1[s] = (d); bk[s] = (c); \
    } else if ((d) < best2[s]) best2[s] = (d); } while (0)

__global__ void __launch_bounds__(256, 2)
mma_argmin_kernel() {
    extern __shared__ char smem[];
    const unsigned sb = smem_u32(smem);
    const int tid  = threadIdx.x;
    const int lane = tid & 31;
    const int warp = tid >> 5;
    const int warp_m = warp & 1;       // 0..1 (32 rows each)
    const int warp_n = warp >> 1;      // 0..3 (16 codes each)
    const int rowBase = blockIdx.x * 64;

    float* s_esq = (float*)(smem + SM_ESQ);
    for (int i = tid; i < KCODES; i += 256) s_esq[i] = g_esq[i];

    // ---- A resident: 64 x 256 fp16, swizzled 16B units ----
#pragma unroll
    for (int it = 0; it < 8; it++) {
        int idx = tid + it * 256;
        int row = idx >> 5, u = idx & 31;
        const void* src = g_zh + ((size_t)(rowBase + row) << 8) + u * 8;
        unsigned dst = sb + SM_A + row * 512 + ((u ^ (row & 7)) << 4);
        cp16(dst, src);
    }
    load_B_tile(sb, 0, 0, tid);
    CP_COMMIT();                 // G0: A + B0
    load_B_tile(sb, 1, 1, tid);
    CP_COMMIT();                 // G1: B1

    // ldmatrix per-lane base addresses
    unsigned a_base[2], b_base;
    int a_x[2], b_x;
    const int a_uo = lane >> 4;          // 0/1
    const int b_uo = (lane >> 3) & 1;    // 0/1
#pragma unroll
    for (int mi = 0; mi < 2; mi++) {
        int r = warp_m * 32 + mi * 16 + (lane & 15);
        a_base[mi] = sb + SM_A + r * 512;
        a_x[mi] = r & 7;
    }
    {
        int r = warp_n * 16 + (lane & 7) + ((lane & 16) ? 8 : 0);
        b_base = sb + SM_B + r * 512;
        b_x = r & 7;
    }

    float best1[4], best2[4];
    int   bk[4];
#pragma unroll
    for (int s = 0; s < 4; s++) { best1[s] = 3.4e38f; best2[s] = 3.4e38f; bk[s] = 0; }

    for (int nt = 0; nt < 16; nt++) {
        if (nt < 15) { CP_WAIT(1); } else { CP_WAIT(0); }
        __syncthreads();

        const unsigned boff = (unsigned)((nt & 1) * 32768);
        float acc[2][2][4];
#pragma unroll
        for (int mi = 0; mi < 2; mi++)
#pragma unroll
            for (int ni = 0; ni < 2; ni++)
#pragma unroll
                for (int q = 0; q < 4; q++) acc[mi][ni][q] = 0.0f;

#pragma unroll
        for (int ks = 0; ks < 16; ks++) {
            unsigned af[2][4];
#pragma unroll
            for (int mi = 0; mi < 2; mi++) {
                unsigned u = (unsigned)((ks * 2 + a_uo) ^ a_x[mi]) << 4;
                LDSM4(af[mi][0], af[mi][1], af[mi][2], af[mi][3], a_base[mi] + u);
            }
            unsigned bf[2][2];
            {
                unsigned u = (unsigned)((ks * 2 + b_uo) ^ b_x) << 4;
                unsigned q0, q1, q2, q3;
                LDSM4(q0, q1, q2, q3, b_base + boff + u);
                bf[0][0] = q0; bf[0][1] = q1;
                bf[1][0] = q2; bf[1][1] = q3;
            }
#pragma unroll
            for (int mi = 0; mi < 2; mi++)
#pragma unroll
                for (int ni = 0; ni < 2; ni++)
                    MMA16816(acc[mi][ni], af[mi], bf[ni]);
        }

        // epilogue: fold esq, update per-thread top-2
        const int cbase = nt * 64 + warp_n * 16 + (lane & 3) * 2;
#pragma unroll
        for (int ni = 0; ni < 2; ni++) {
            int c0 = cbase + ni * 8;
            float e0 = s_esq[c0], e1 = s_esq[c0 + 1];
#pragma unroll
            for (int mi = 0; mi < 2; mi++) {
                float d0 = acc[mi][ni][0] + e0;
                float d1 = acc[mi][ni][1] + e1;
                float d2 = acc[mi][ni][2] + e0;
                float d3 = acc[mi][ni][3] + e1;
                int s = mi * 2;
                UPD(s, d0, c0); UPD(s, d1, c0 + 1);
                UPD(s + 1, d2, c0); UPD(s + 1, d3, c0 + 1);
            }
        }
        __syncthreads();
        if (nt + 2 < 16) { load_B_tile(sb, nt + 2, nt & 1, tid); CP_COMMIT(); }
    }

    // quad (lane%4) butterfly merge of top-2
#pragma unroll
    for (int off = 1; off <= 2; off <<= 1) {
#pragma unroll
        for (int s = 0; s < 4; s++) {
            float o1 = __shfl_xor_sync(0xffffffffu, best1[s], off);
            float o2 = __shfl_xor_sync(0xffffffffu, best2[s], off);
            int   ok = __shfl_xor_sync(0xffffffffu, bk[s], off);
            if (o1 < best1[s] || (o1 == best1[s] && ok < bk[s])) {
                best2[s] = fminf(best1[s], o2);
                best1[s] = o1; bk[s] = ok;
            } else {
                best2[s] = fminf(best2[s], o1);
            }
        }
    }

    // cross-warp (4 warp_n columns) merge via smem (reuse A region)
    float* f1 = (float*)(smem + SM_A);
    float* f2 = f1 + 256;
    int*   kk = (int*)(f2 + 256);
    __syncthreads();
    if ((lane & 3) == 0) {
        int rq = lane >> 2;
#pragma unroll
        for (int s = 0; s < 4; s++) {
            int rl = warp_m * 32 + (s >> 1) * 16 + (s & 1) * 8 + rq;
            f1[warp_n * 64 + rl] = best1[s];
            f2[warp_n * 64 + rl] = best2[s];
            kk[warp_n * 64 + rl] = bk[s];
        }
    }
    __syncthreads();
    if (tid < 64) {
        float m1 = f1[tid], m2 = f2[tid];
        int   mk = kk[tid];
#pragma unroll
        for (int w = 1; w < 4; w++) {
            float b1 = f1[w * 64 + tid], b2 = f2[w * 64 + tid];
            int   bkk = kk[w * 64 + tid];
            if (b1 < m1 || (b1 == m1 && bkk < mk)) {
                m2 = fminf(m1, b2); m1 = b1; mk = bkk;
            } else {
                m2 = fminf(m2, b1);
            }
        }
        int row = rowBase + tid;
        g_idx[row] = mk;
        if (m2 - m1 < MARGIN) {
            int p = atomicAdd(&g_namb, 1);
            g_amb[p] = row;
            g_fb[row] = ~0ull;
        }
    }
}

// ============================================================
// Exact fp32 recompute for ambiguous rows, COALESCED via E^T.
// Grid 2048 = 512 row-groups x 4 code-quarters.
// Thread owns code k; loop d reads g_et[d*1024+k] (lane-consecutive).
// ============================================================
__global__ void __launch_bounds__(256)
fallback_kernel(const float* __restrict__ Z) {
    __shared__ float zrow[8][DIM];
    __shared__ unsigned long long red[256];
    __shared__ int s_rid[8];
    const int grp = blockIdx.x >> 2;
    const int qtr = blockIdx.x & 3;
    const int namb = g_namb;
    const int k = qtr * 256 + threadIdx.x;
    const float esq = g_esq[k];
    const float* et = g_et + k;

    for (int base = grp * 8; base < namb; base += 512 * 8) {
        const int m = min(8, namb - base);
        if (threadIdx.x < m) s_rid[threadIdx.x] = g_amb[base + threadIdx.x];
        __syncthreads();
        for (int t = threadIdx.x; t < m * 64; t += 256) {
            int r = t >> 6, q = t & 63;
            ((float4*)zrow[r])[q] = ((const float4*)(Z + (size_t)s_rid[r] * DIM))[q];
        }
        __syncthreads();

        float zs[8];
#pragma unroll
        for (int r = 0; r < 8; r++) zs[r] = (r < m) ? g_zsq[s_rid[r]] : 0.0f;

        float dot[8];
#pragma unroll
        for (int r = 0; r < 8; r++) dot[r] = 0.0f;
#pragma unroll 4
        for (int d = 0; d < DIM; d++) {
            float e = et[(size_t)d * KCODES];   // coalesced across lanes
#pragma unroll
            for (int r = 0; r < 8; r++)
                dot[r] += e * zrow[r][d];
        }
        for (int r = 0; r < m; r++) {
            float dist = (zs[r] + esq) - 2.0f * dot[r];
            red[threadIdx.x] =
                ((unsigned long long)__float_as_uint(dist) << 32) | (unsigned)k;
            __syncthreads();
#pragma unroll
            for (int s = 128; s; s >>= 1) {
                if (threadIdx.x < s && red[threadIdx.x + s] < red[threadIdx.x])
                    red[threadIdx.x] = red[threadIdx.x + s];
                __syncthreads();
            }
            if (threadIdx.x == 0)
                atomicMin(&g_fb[s_rid[r]], red[0]);
            __syncthreads();
        }
        __syncthreads();
    }
}

__global__ void fixup_kernel() {
    for (int i = blockIdx.x * blockDim.x + threadIdx.x; i < g_namb;
         i += gridDim.x * blockDim.x) {
        int row = g_amb[i];
        g_idx[row] = (int)(g_fb[row] & 0xFFFFFFFFull);
    }
}

// ============================================================
// z_q_st elementwise + idx output + loss + cluster-size histogram.
// ============================================================
__global__ void zq_kernel(const float* __restrict__ Z,
                          const float* __restrict__ E,
                          float* __restrict__ out) {
    __shared__ double lred[8];
    int warp = threadIdx.x >> 5;
    int lane = threadIdx.x & 31;
    int row  = blockIdx.x * 8 + warp;
    int ci   = g_idx[row];

    const float4* zp = (const float4*)(Z + (size_t)row * DIM);
    const float4* qp = (const float4*)(E + (size_t)ci * DIM);
    float4*       op = (float4*)(out + OFF_ZQ + (size_t)row * DIM);

    float sq = 0.0f;
#pragma unroll
    for (int l = 0; l < 2; l++) {
        float4 z = zp[lane * 2 + l];
        float4 q = qp[lane * 2 + l];
        float dx = q.x - z.x, dy = q.y - z.y, dz = q.z - z.z, dw4 = q.w - z.w;
        float4 o;
        o.x = z.x + dx; o.y = z.y + dy; o.z = z.z + dz; o.w = z.w + dw4;
        op[lane * 2 + l] = o;
        sq += dx * dx + dy * dy + dz * dz + dw4 * dw4;
    }
#pragma unroll
    for (int o = 16; o; o >>= 1) sq += __shfl_down_sync(0xffffffffu, sq, o);
    if (lane == 0) {
        lred[warp] = (double)sq;
        out[OFF_IDX + row] = (float)ci;
        atomicAdd(&g_cnt[ci], 1);
    }
    __syncthreads();
    if (threadIdx.x == 0) {
        double s = 0.0;
#pragma unroll
        for (int w = 0; w < 8; w++) s += lred[w];
        atomicAdd(&g_loss, s);
    }
}

// ============================================================
// Counting sort: scan -> scatter -> dw.
// ============================================================
__global__ void scan_kernel() {
    __shared__ int s[KCODES];
    int t = threadIdx.x;
    s[t] = g_cnt[t];
    __syncthreads();
#pragma unroll
    for (int o = 1; o < KCODES; o <<= 1) {
        int v = s[t];
        int u = (t >= o) ? s[t - o] : 0;
        __syncthreads();
        s[t] = v + u;
        __syncthreads();
    }
    g_off[t + 1] = s[t];
    if (t == 0) g_off[0] = 0;
}

__global__ void scatter_kernel() {
    int i = blockIdx.x * blockDim.x + threadIdx.x;
    if (i < BATCH) {
        int c = g_idx[i];
        int pos = atomicAdd(&g_cur[c], 1);
        g_rows[g_off[c] + pos] = i;
    }
}

__global__ void dw_kernel(const float* __restrict__ Z) {
    int k = blockIdx.x;
    int d = threadIdx.x;
    int s = g_off[k], e = g_off[k + 1];
    float acc0 = 0.0f, acc1 = 0.0f;
    int i = s;
    for (; i + 1 < e; i += 2) {
        acc0 += Z[(size_t)g_rows[i] * DIM + d];
        acc1 += Z[(size_t)g_rows[i + 1] * DIM + d];
    }
    if (i < e) acc0 += Z[(size_t)g_rows[i] * DIM + d];
    g_dw[k * DIM + d] = acc0 + acc1;
}

// ============================================================
__global__ void finalize_kernel(const float* __restrict__ ecs_in,
                                float* __restrict__ out) {
    __shared__ float red[KCODES];
    int k = threadIdx.x;

    float cs   = (float)g_cnt[k];
    float necs = DECAY_F * ecs_in[k] + OMD_F * cs;
    out[OFF_ECS + k] = necs;

    red[k] = necs;
    __syncthreads();
#pragma unroll
    for (int s = 512; s; s >>= 1) {
        if (k < s) red[k] += red[k + s];
        __syncthreads();
    }
    float n = red[0];
    __syncthreads();

    float p = cs * (1.0f / (float)BATCH);
    red[k] = p * logf(p + 1e-10f);
    __syncthreads();
#pragma unroll
    for (int s = 512; s; s >>= 1) {
        if (k < s) red[k] += red[k + s];
        __syncthreads();
    }
    if (k == 0) {
        out[OFF_PERP] = expf(-red[0]);
        out[OFF_LOSS] = (float)(0.25 * (g_loss / ((double)BATCH * (double)DIM)));
    }

    float smoothed = (necs + 1e-5f) / (n + (float)(KCODES * 1e-5)) * n;
    g_smoothed[k] = smoothed;
}

__global__ void emaw_kernel(const float* __restrict__ ema_w,
                            float* __restrict__ out) {
    int idx = blockIdx.x * DIM + threadIdx.x;
    int k   = idx >> 8;
    float w = DECAY_F * ema_w[idx] + OMD_F * g_dw[idx];
    out[OFF_EMAW + idx] = w;
    out[OFF_EMB + idx]  = w / g_smoothed[k];
}

// ============================================================
extern "C" void kernel_launch(void* const* d_in, const int* in_sizes, int n_in,
                              void* d_out, int out_size) {
    const float* z_e  = (const float*)d_in[0];
    const float* emb  = (const float*)d_in[1];
    const float* ecs  = (const float*)d_in[2];
    const float* emaw = (const float*)d_in[3];
    float* out = (float*)d_out;

    cudaFuncSetAttribute(mma_argmin_kernel,
                         cudaFuncAttributeMaxDynamicSharedMemorySize, SM_TOTAL);

    init_kernel<<<(KCODES + 255) / 256, 256>>>();
    convert_z_kernel<<<BATCH / 8, 256>>>(z_e);
    convert_e_kernel<<<KCODES / 8, 256>>>(emb);
    mma_argmin_kernel<<<BATCH / 64, 256, SM_TOTAL>>>();    // 4th launch -> profiled
    fallback_kernel<<<2048, 256>>>(z_e);
    fixup_kernel<<<16, 256>>>();
    zq_kernel<<<BATCH / 8, 256>>>(z_e, emb, out);
    scan_kernel<<<1, KCODES>>>();
    scatter_kernel<<<BATCH / 256, 256>>>();
    dw_kernel<<<KCODES, DIM>>>(z_e);
    finalize_kernel<<<1, KCODES>>>(ecs, out);
    emaw_kernel<<<KCODES, DIM>>>(emaw, out);
}